// round 2
// baseline (speedup 1.0000x reference)
#include <cuda_runtime.h>
#include <cuda_bf16.h>

// Problem constants: B=16, N=256, D=64. G = rows per block.
#define Bn 16
#define Nn 256
#define Dn 64
#define G  4

// Fully fused kernel. Grid = B * N/G = 1024 blocks, 256 threads.
// Each block:
//   1. recomputes v = W^T a (threads 0..63) and c = a.bW + ba/2 (warp 2)
//   2. computes s_j = emb[b,j].v + c for all 256 j (one per thread)
//   3. softmax for its G rows (single fused 4-row block reduction)
//   4. streams value[b, i0..i0+G, :, :] = ei (x) ej  reading emb[b] ONCE
__global__ __launch_bounds__(256) void fused_kernel(
        const float* __restrict__ emb,
        const float* __restrict__ W,
        const float* __restrict__ bW,
        const float* __restrict__ a,
        const float* __restrict__ ba,
        float* __restrict__ out_alpha,   // [B,N,N]
        float* __restrict__ out_value) { // [B,N,N,D]
    const int tid = threadIdx.x;
    const int b   = blockIdx.x >> 6;          // blockIdx / (N/G)
    const int i0  = (blockIdx.x & 63) << 2;   // first of G rows

    __shared__ float  sv[Dn];
    __shared__ float  sc;
    __shared__ float  ss[Nn];
    __shared__ float4 sei[G][Dn / 4];
    __shared__ float  red[8][G];

    const float4* embB4 = (const float4*)(emb + (size_t)b * Nn * Dn);

    // ---- 1. v, c, and ei staging (disjoint warps) ----
    if (tid < 64) {
        float acc = 0.f;
#pragma unroll 8
        for (int e = 0; e < Dn; e++) acc = fmaf(a[e], W[e * Dn + tid], acc);
        sv[tid] = acc;
    } else if (tid < 96) {
        int l = tid - 64;
        float acc = a[l] * bW[l] + a[l + 32] * bW[l + 32];
#pragma unroll
        for (int o = 16; o; o >>= 1) acc += __shfl_xor_sync(0xFFFFFFFFu, acc, o);
        if (l == 0) sc = acc + 0.5f * ba[0];
    } else if (tid < 160) {
        int t = tid - 96;                     // 0..63
        int g = t >> 4, q = t & 15;
        sei[g][q] = embB4[(i0 + g) * (Dn / 4) + q];
    }
    __syncthreads();

    // ---- 2. s_j for all j (also warms emb[b] in L2) ----
    {
        const float4* myrow = embB4 + tid * (Dn / 4);
        const float4* v4 = (const float4*)sv;
        float acc = 0.f;
#pragma unroll
        for (int k = 0; k < Dn / 4; k++) {
            float4 e = myrow[k], v = v4[k];
            acc += e.x * v.x + e.y * v.y + e.z * v.z + e.w * v.w;
        }
        ss[tid] = acc + sc;
    }
    __syncthreads();

    // ---- 3. softmax for G rows at once ----
    float x[G], ex[G];
    const float sj = ss[tid];
#pragma unroll
    for (int g = 0; g < G; g++) {
        float t = ss[i0 + g] + sj;
        x[g] = (t >= 0.f) ? t : 0.01f * t;    // leaky_relu
    }
    float m[G];
#pragma unroll
    for (int g = 0; g < G; g++) {
        m[g] = x[g];
#pragma unroll
        for (int o = 16; o; o >>= 1) m[g] = fmaxf(m[g], __shfl_xor_sync(0xFFFFFFFFu, m[g], o));
    }
    if ((tid & 31) == 0)
#pragma unroll
        for (int g = 0; g < G; g++) red[tid >> 5][g] = m[g];
    __syncthreads();
#pragma unroll
    for (int g = 0; g < G; g++) {
        float bm = red[0][g];
#pragma unroll
        for (int w = 1; w < 8; w++) bm = fmaxf(bm, red[w][g]);
        ex[g] = __expf(x[g] - bm);
    }
    float sm[G];
#pragma unroll
    for (int g = 0; g < G; g++) {
        sm[g] = ex[g];
#pragma unroll
        for (int o = 16; o; o >>= 1) sm[g] += __shfl_xor_sync(0xFFFFFFFFu, sm[g], o);
    }
    __syncthreads();                          // red reads done before overwrite
    if ((tid & 31) == 0)
#pragma unroll
        for (int g = 0; g < G; g++) red[tid >> 5][g] = sm[g];
    __syncthreads();
    {
        const size_t rowA = (size_t)blockIdx.x * G * Nn;
#pragma unroll
        for (int g = 0; g < G; g++) {
            float tot = red[0][g];
#pragma unroll
            for (int w = 1; w < 8; w++) tot += red[w][g];
            out_alpha[rowA + (size_t)g * Nn + tid] = __fdividef(ex[g], tot);
        }
    }

    // ---- 4. value rows: read ej once, write G rows ----
    float4 eir[G];
#pragma unroll
    for (int g = 0; g < G; g++) eir[g] = sei[g][tid & 15];

    float4* ov = (float4*)out_value;
    const size_t base = (size_t)blockIdx.x * G * (Nn * Dn / 4);  // float4 units
#pragma unroll
    for (int k = 0; k < Nn * Dn / 4 / 256; k++) {                // 16 iters
        const int idx = k * 256 + tid;                           // (j,d4) packed
        const float4 ej = embB4[idx];
#pragma unroll
        for (int g = 0; g < G; g++) {
            float4 r;
            r.x = eir[g].x * ej.x;
            r.y = eir[g].y * ej.y;
            r.z = eir[g].z * ej.z;
            r.w = eir[g].w * ej.w;
            __stcs(&ov[base + (size_t)g * (Nn * Dn / 4) + idx], r);
        }
    }
}

extern "C" void kernel_launch(void* const* d_in, const int* in_sizes, int n_in,
                              void* d_out, int out_size) {
    const float* emb = (const float*)d_in[0];
    const float* W   = (const float*)d_in[1];
    const float* bW  = (const float*)d_in[2];
    const float* a   = (const float*)d_in[3];
    const float* ba  = (const float*)d_in[4];

    float* out_alpha = (float*)d_out;                        // B*N*N floats
    float* out_value = (float*)d_out + (size_t)Bn * Nn * Nn; // B*N*N*D floats

    fused_kernel<<<Bn * (Nn / G), 256>>>(emb, W, bW, a, ba, out_alpha, out_value);
}